// round 7
// baseline (speedup 1.0000x reference)
#include <cuda_runtime.h>
#include <cstddef>

// Problem constants (match reference)
#define BATCH 256
#define SEQ   780
#define DIM   1024
#define MAXT  195
#define THREADS 128          // 128 lanes x 32B = one 4KB row per iteration
#define CTAS_PER_SM 12
#define NUM_SMS 148          // GB300 has 152; 148 keeps full waves on either
#define TOTAL_TOKENS (BATCH * MAXT)

// 256-bit global load, L1-bypass / non-coherent (sm_100+: LDG.E.256)
__device__ __forceinline__ void ldg256_nc(const float* p, float* r) {
    asm volatile(
        "ld.global.nc.v8.f32 {%0,%1,%2,%3,%4,%5,%6,%7}, [%8];"
        : "=f"(r[0]), "=f"(r[1]), "=f"(r[2]), "=f"(r[3]),
          "=f"(r[4]), "=f"(r[5]), "=f"(r[6]), "=f"(r[7])
        : "l"(p));
}

// 256-bit global store (sm_100+: STG.256)
__device__ __forceinline__ void stg256(float* p, const float* r) {
    asm volatile(
        "st.global.v8.f32 [%0], {%1,%2,%3,%4,%5,%6,%7,%8};"
        :: "l"(p),
           "f"(r[0]), "f"(r[1]), "f"(r[2]), "f"(r[3]),
           "f"(r[4]), "f"(r[5]), "f"(r[6]), "f"(r[7])
        : "memory");
}

// Persistent grid-stride kernel: each CTA loops over (b, j) token slots.
// Per iteration: valid -> 4 independent 256-bit gathers + average + store;
// invalid -> one 256-bit zero store (output buffer is poisoned; must write).
__global__ void __launch_bounds__(THREADS, CTAS_PER_SM)
avg_pool_merge_pers_kernel(const float* __restrict__ hs,
                           const int*   __restrict__ grid_thw,
                           float*       __restrict__ out,
                           float*       __restrict__ out_att)
{
    const int t      = threadIdx.x;          // 8-float lane [0, 128)
    const int stride = gridDim.x;            // total CTAs

    for (int tok = blockIdx.x; tok < TOTAL_TOKENS; tok += stride) {
        const int b = tok / MAXT;
        const int j = tok - b * MAXT;

        const int W2 = grid_thw[b * 3 + 2] >> 1;
        const int Hp = grid_thw[b * 3 + 1] >> 2;
        const int Wp = W2 >> 1;
        const int n_out = Hp * Wp;

        float* o = out + (size_t)tok * DIM + t * 8;

        if (j >= n_out) {
            float z[8] = {0.f, 0.f, 0.f, 0.f, 0.f, 0.f, 0.f, 0.f};
            stg256(o, z);
            if (t == 0 && out_att) out_att[tok] = 0.f;
            continue;
        }

        const int r = j / Wp;
        const int c = j - r * Wp;
        const int base = (2 * r) * W2 + 2 * c;  // top-left of the 2x2 window

        const float* srow = hs + (size_t)b * SEQ * DIM
                               + (size_t)base * DIM + t * 8;

        // 4 independent 256-bit loads (the MLP depth that works)
        float v0[8], v1[8], v2[8], v3[8];
        ldg256_nc(srow,                          v0);
        ldg256_nc(srow + DIM,                    v1);
        ldg256_nc(srow + (size_t)W2 * DIM,       v2);
        ldg256_nc(srow + (size_t)(W2 + 1) * DIM, v3);

        float s[8];
#pragma unroll
        for (int i = 0; i < 8; i++)
            s[i] = (v0[i] + v1[i] + v2[i] + v3[i]) * 0.25f;

        stg256(o, s);

        if (t == 0 && out_att) out_att[tok] = 1.f;
    }
}

extern "C" void kernel_launch(void* const* d_in, const int* in_sizes, int n_in,
                              void* d_out, int out_size)
{
    const float* hs       = (const float*)d_in[0];  // [B, S, D] float32
    // d_in[1] = attention_mask (values unused by reference math)
    const int*   grid_thw = (const int*)d_in[2];    // [B, 3] int32

    float* out = (float*)d_out;
    const long long main_elems = (long long)BATCH * MAXT * DIM;
    const long long att_elems  = (long long)BATCH * MAXT;
    float* out_att = ((long long)out_size >= main_elems + att_elems)
                         ? out + main_elems : nullptr;

    const int grid = NUM_SMS * CTAS_PER_SM;   // 1776 persistent CTAs
    avg_pool_merge_pers_kernel<<<grid, THREADS>>>(hs, grid_thw, out, out_att);
}

// round 8
// speedup vs baseline: 1.1521x; 1.1521x over previous
#include <cuda_runtime.h>
#include <cstddef>

// Problem constants (match reference)
#define BATCH 256
#define SEQ   780
#define DIM   1024
#define MAXT  195
#define THREADS 256   // two 128-lane halves; each half owns one pooled token

// 256-bit global load, L1-bypass / non-coherent (sm_100+: LDG.E.256)
__device__ __forceinline__ void ldg256_nc(const float* p, float* r) {
    asm volatile(
        "ld.global.nc.v8.f32 {%0,%1,%2,%3,%4,%5,%6,%7}, [%8];"
        : "=f"(r[0]), "=f"(r[1]), "=f"(r[2]), "=f"(r[3]),
          "=f"(r[4]), "=f"(r[5]), "=f"(r[6]), "=f"(r[7])
        : "l"(p));
}

// 256-bit global store (sm_100+: STG.256)
__device__ __forceinline__ void stg256(float* p, const float* r) {
    asm volatile(
        "st.global.v8.f32 [%0], {%1,%2,%3,%4,%5,%6,%7,%8};"
        :: "l"(p),
           "f"(r[0]), "f"(r[1]), "f"(r[2]), "f"(r[3]),
           "f"(r[4]), "f"(r[5]), "f"(r[6]), "f"(r[7])
        : "memory");
}

// Flat launch, two pooled tokens per CTA split across thread halves.
// Lanes [0,128): token 2*blockIdx.x; lanes [128,256): token 2*blockIdx.x+1.
// Per thread: 4 independent 256-bit loads (proven MLP depth) + 1 store.
__global__ void __launch_bounds__(THREADS, 6)
avg_pool_merge_v8x2_kernel(const float* __restrict__ hs,
                           const int*   __restrict__ grid_thw,
                           float*       __restrict__ out,
                           float*       __restrict__ out_att)
{
    const int b    = blockIdx.y;
    const int half = threadIdx.x >> 7;            // 0 or 1
    const int t    = threadIdx.x & 127;           // 8-float lane within token
    const int j    = blockIdx.x * 2 + half;       // pooled token index

    const int W2 = grid_thw[b * 3 + 2] >> 1;
    const int Hp = grid_thw[b * 3 + 1] >> 2;
    const int Wp = W2 >> 1;
    const int n_out = Hp * Wp;

    const bool inJ = (j < MAXT);                  // grid.x = ceil(MAXT/2): last half may overhang
    if (!inJ) return;

    float* o = out + ((size_t)b * MAXT + j) * DIM + t * 8;

    if (j >= n_out) {
        float z[8] = {0.f, 0.f, 0.f, 0.f, 0.f, 0.f, 0.f, 0.f};
        stg256(o, z);
        if (t == 0 && out_att) out_att[(size_t)b * MAXT + j] = 0.f;
        return;
    }

    const int r = j / Wp;
    const int c = j - r * Wp;
    const int base = (2 * r) * W2 + 2 * c;        // top-left of the 2x2 window

    const float* srow = hs + (size_t)b * SEQ * DIM
                           + (size_t)base * DIM + t * 8;

    float v0[8], v1[8], v2[8], v3[8];
    ldg256_nc(srow,                          v0);
    ldg256_nc(srow + DIM,                    v1);
    ldg256_nc(srow + (size_t)W2 * DIM,       v2);
    ldg256_nc(srow + (size_t)(W2 + 1) * DIM, v3);

    float s[8];
#pragma unroll
    for (int i = 0; i < 8; i++)
        s[i] = (v0[i] + v1[i] + v2[i] + v3[i]) * 0.25f;

    stg256(o, s);

    if (t == 0 && out_att) out_att[(size_t)b * MAXT + j] = 1.f;
}

extern "C" void kernel_launch(void* const* d_in, const int* in_sizes, int n_in,
                              void* d_out, int out_size)
{
    const float* hs       = (const float*)d_in[0];  // [B, S, D] float32
    // d_in[1] = attention_mask (values unused by reference math)
    const int*   grid_thw = (const int*)d_in[2];    // [B, 3] int32

    float* out = (float*)d_out;
    const long long main_elems = (long long)BATCH * MAXT * DIM;
    const long long att_elems  = (long long)BATCH * MAXT;
    float* out_att = ((long long)out_size >= main_elems + att_elems)
                         ? out + main_elems : nullptr;

    dim3 grid((MAXT + 1) / 2, BATCH);   // 98 x 256 CTAs
    avg_pool_merge_v8x2_kernel<<<grid, THREADS>>>(hs, grid_thw, out, out_att);
}